// round 10
// baseline (speedup 1.0000x reference)
#include <cuda_runtime.h>
#include <cuda_fp16.h>
#include <cstdint>

#define B_ 128
#define T_ 32
#define NS_ 200
#define ROWS_TOTAL 25600
#define G_ 256
#define RPC 64
#define NCTA 400
#define TPB 512
#define GS 261
#define HS 36
#define OF_GATE 0
#define OF_H0 16704
#define OF_H1 19008
#define OF_XG 21312
#define OF_W0C 22336
#define OF_BL1 22592
#define OF_WP 22848
#define OF_LAG 22976
#define OF_RED 23040
#define SM_WORDS 24064

__device__ float g_xproj[B_*T_*G_];
__device__ float g_eps[T_*ROWS_TOTAL];

__device__ __forceinline__ uint32_t rotl32(uint32_t x,int d){return (x<<d)|(x>>(32-d));}
__device__ __forceinline__ float sigf(float x){return __fdividef(1.0f,1.0f+__expf(-x));}
__device__ __forceinline__ float tanhf_(float x){return 1.0f-__fdividef(2.0f,1.0f+__expf(2.0f*x));}
__device__ __forceinline__ float softplusf_(float x){return fmaxf(x,0.0f)+log1pf(expf(-fabsf(x)));}

__device__ __forceinline__ float erfinv_xla(float x){
  float w=-log1pf(-x*x),p;
  if(w<5.0f){w=w-2.5f;
    p=2.81022636e-08f;p=fmaf(p,w,3.43273939e-07f);p=fmaf(p,w,-3.5233877e-06f);
    p=fmaf(p,w,-4.39150654e-06f);p=fmaf(p,w,0.00021858087f);p=fmaf(p,w,-0.00125372503f);
    p=fmaf(p,w,-0.00417768164f);p=fmaf(p,w,0.246640727f);p=fmaf(p,w,1.50140941f);
  }else{w=sqrtf(w)-3.0f;
    p=-0.000200214257f;p=fmaf(p,w,0.000100950558f);p=fmaf(p,w,0.00134934322f);
    p=fmaf(p,w,-0.00367342844f);p=fmaf(p,w,0.00573950773f);p=fmaf(p,w,-0.0076224613f);
    p=fmaf(p,w,0.00943887047f);p=fmaf(p,w,1.00167406f);p=fmaf(p,w,2.83297682f);}
  return p*x;
}
__device__ __forceinline__ float bits_to_normal(uint32_t bits){
  float u=__uint_as_float((bits>>9)|0x3f800000u)-1.0f;
  float x=fmaf(u,2.0f,-0.99999994f);
  x=fmaxf(-0.99999994f,x);
  return 1.41421356f*erfinv_xla(x);
}

__global__ void setup_kernel(const float* __restrict__ dec_cont,const float* __restrict__ emb0,
    const float* __restrict__ emb1,const float* __restrict__ Wih0,const float* __restrict__ bih0,
    const float* __restrict__ bhh0,const int* __restrict__ dec_cat){
  if(blockIdx.x>=4096){
    uint32_t j=(blockIdx.x-4096)*blockDim.x+threadIdx.x;
    if(j>=(uint32_t)(T_*ROWS_TOTAL))return;
    const uint32_t ks0=0u,ks1=42u,ks2=0x1BD11BDAu^42u;
    uint32_t x0=0u,x1=j;
    x0+=ks0;x1+=ks1;
#define RND_(r){x0+=x1;x1=rotl32(x1,(r));x1^=x0;}
    RND_(13)RND_(15)RND_(26)RND_(6)  x0+=ks1;x1+=ks2+1u;
    RND_(17)RND_(29)RND_(16)RND_(24) x0+=ks2;x1+=ks0+2u;
    RND_(13)RND_(15)RND_(26)RND_(6)  x0+=ks0;x1+=ks1+3u;
    RND_(17)RND_(29)RND_(16)RND_(24) x0+=ks1;x1+=ks2+4u;
    RND_(13)RND_(15)RND_(26)RND_(6)  x0+=ks2;x1+=ks0+5u;
#undef RND_
    g_eps[j]=bits_to_normal(x0^x1);
    return;
  }
  int bt=blockIdx.x,g=threadIdx.x;
  __shared__ float feat[32];
  if(g<32){
    float v=0.0f;
    if(g>=1&&g<6)v=dec_cont[bt*6+g];
    else if(g>=6&&g<16)v=emb0[dec_cat[bt*2]*10+(g-6)];
    else if(g>=16)v=emb1[dec_cat[bt*2+1]*16+(g-16)];
    feat[g]=v;
  }
  __syncthreads();
  float acc=bih0[g]+bhh0[g];
  #pragma unroll
  for(int k=1;k<32;k++)acc=fmaf(Wih0[g*32+k],feat[k],acc);
  g_xproj[bt*G_+g]=acc;
}

#define MMA(d,a,bb0,bb1) \
  asm volatile("mma.sync.aligned.m16n8k16.row.col.f32.f16.f16.f32 " \
    "{%0,%1,%2,%3}, {%4,%5,%6,%7}, {%8,%9}, {%0,%1,%2,%3};" \
    : "+f"((d)[0]),"+f"((d)[1]),"+f"((d)[2]),"+f"((d)[3]) \
    : "r"((a)[0]),"r"((a)[1]),"r"((a)[2]),"r"((a)[3]),"r"(bb0),"r"(bb1))

__device__ __forceinline__ uint32_t f2h2(float lo,float hi){
  __half2 h=__floats2half2_rn(lo,hi);
  return *reinterpret_cast<uint32_t*>(&h);
}

__global__ __launch_bounds__(TPB,1)
void deepar_mma(const float* __restrict__ ts,const float* __restrict__ one_off,
    const float* __restrict__ Wih0,const float* __restrict__ Whh0,
    const float* __restrict__ Wih1,const float* __restrict__ Whh1,
    const float* __restrict__ bih1,const float* __restrict__ bhh1,
    const float* __restrict__ Wproj,const float* __restrict__ bproj,
    const float* __restrict__ h0in,const float* __restrict__ c0in,
    float* __restrict__ out)
{
  extern __shared__ float sm[];
  uint32_t* smu=(uint32_t*)sm;
  const int tid=threadIdx.x;
  const int w=tid>>5,lane=tid&31;
  const int la=lane>>2,lb=lane&3;
  const int gr0=blockIdx.x*RPC;
  const int b0=gr0/NS_,bL=(gr0+RPC-1)/NS_;
  const int r=tid&63,cb=tid>>6,ch0=cb*8;   // 8 channels per thread
  const int myb=(gr0+r)/NS_;
  const int bsel=(myb!=b0)?1:0;

  // warp w owns gates [16w,16w+16): one m16 A-tile per matrix per kt
  uint32_t aW0[4][4],aI1[4][4],aH1[4][4];
  #pragma unroll
  for(int kt=0;kt<4;kt++){
    int m=w*16+la,k=kt*16+lb*2;
    aW0[kt][0]=f2h2(Whh0[m*64+k],Whh0[m*64+k+1]);
    aW0[kt][1]=f2h2(Whh0[(m+8)*64+k],Whh0[(m+8)*64+k+1]);
    aW0[kt][2]=f2h2(Whh0[m*64+k+8],Whh0[m*64+k+9]);
    aW0[kt][3]=f2h2(Whh0[(m+8)*64+k+8],Whh0[(m+8)*64+k+9]);
    aI1[kt][0]=f2h2(Wih1[m*64+k],Wih1[m*64+k+1]);
    aI1[kt][1]=f2h2(Wih1[(m+8)*64+k],Wih1[(m+8)*64+k+1]);
    aI1[kt][2]=f2h2(Wih1[m*64+k+8],Wih1[m*64+k+9]);
    aI1[kt][3]=f2h2(Wih1[(m+8)*64+k+8],Wih1[(m+8)*64+k+9]);
    aH1[kt][0]=f2h2(Whh1[m*64+k],Whh1[m*64+k+1]);
    aH1[kt][1]=f2h2(Whh1[(m+8)*64+k],Whh1[(m+8)*64+k+1]);
    aH1[kt][2]=f2h2(Whh1[m*64+k+8],Whh1[m*64+k+9]);
    aH1[kt][3]=f2h2(Whh1[(m+8)*64+k+8],Whh1[(m+8)*64+k+9]);
  }

  if(tid<256){
    sm[OF_W0C+tid]=Wih0[tid*32];
    sm[OF_BL1+tid]=bih1[tid]+bhh1[tid];
  }
  if(tid<128)sm[OF_WP+tid]=Wproj[tid];
  if(tid<64)sm[OF_LAG+tid]=one_off[(gr0+tid)/NS_];
  if(tid<512){
    int sel=tid>>8,g=tid&255;
    sm[OF_XG+sel*256+g]=g_xproj[((sel?bL:b0)*T_)*G_+g];
  }
  float c0v[8],c1v[8];
  {
    #pragma unroll
    for(int j=0;j<8;j++){
      int ch=ch0+j;
      c0v[j]=c0in[myb*64+ch];
      c1v[j]=c0in[8192+myb*64+ch];
    }
    __half2* h0p=(__half2*)&smu[OF_H0+r*HS+(ch0>>1)];
    __half2* h1p=(__half2*)&smu[OF_H1+r*HS+(ch0>>1)];
    #pragma unroll
    for(int j=0;j<4;j++){
      int ch=ch0+2*j;
      h0p[j]=__floats2half2_rn(h0in[myb*64+ch],h0in[myb*64+ch+1]);
      h1p[j]=__floats2half2_rn(h0in[8192+myb*64+ch],h0in[8192+myb*64+ch+1]);
    }
  }
  float cen=0.f,scl=1.f,bp0=0.f,bp1=0.f;
  int sb=0,ss=0;
  if(tid<64){
    int sgr=gr0+tid;
    sb=sgr/NS_;ss=sgr-sb*NS_;
    cen=ts[2*sb];scl=ts[2*sb+1];
    bp0=bproj[0];bp1=bproj[1];
  }
  __syncthreads();

  #pragma unroll 1
  for(int t=0;t<T_;t++){
    // phase 1: L0 MMA (+ finalize sample t-1 on tid<64)
    #pragma unroll
    for(int nt=0;nt<8;nt++){
      float d[4]={0,0,0,0};
      #pragma unroll
      for(int kt=0;kt<4;kt++){
        uint32_t b0r=smu[OF_H0+(nt*8+la)*HS+kt*8+lb];
        uint32_t b1r=smu[OF_H0+(nt*8+la)*HS+kt*8+lb+4];
        MMA(d,aW0[kt],b0r,b1r);
      }
      int n0=nt*8+lb*2,m=w*16+la;
      sm[OF_GATE+n0*GS+m]=d[0];     sm[OF_GATE+(n0+1)*GS+m]=d[1];
      sm[OF_GATE+n0*GS+m+8]=d[2];   sm[OF_GATE+(n0+1)*GS+m+8]=d[3];
    }
    if(t>0&&tid<64){
      int tp=t-1;
      float r0=bp0,r1=bp1;
      #pragma unroll
      for(int k=0;k<8;k++){r0+=sm[OF_RED+k*64+tid];r1+=sm[OF_RED+512+k*64+tid];}
      float loc=fmaf(r0,scl,cen);
      float sig=softplusf_(r1)*scl;
      float pred=fmaf(sig,g_eps[tp*ROWS_TOTAL+gr0+tid],loc);
      out[(sb*T_+tp)*NS_+ss]=pred;
      sm[OF_LAG+tid]=(pred-cen)/scl;
    }
    __syncthreads();
    // phase 2: L0 update
    {
      const float lagv=sm[OF_LAG+r];
      const float* xg=&sm[OF_XG+((t&1)*2+bsel)*256];
      const float* gp=&sm[OF_GATE+r*GS];
      float hn[8];
      #pragma unroll
      for(int j=0;j<8;j++){
        int ch=ch0+j;
        float gi=gp[ch]     +fmaf(sm[OF_W0C+ch],lagv,xg[ch]);
        float gf=gp[64+ch]  +fmaf(sm[OF_W0C+64+ch],lagv,xg[64+ch]);
        float gg=gp[128+ch] +fmaf(sm[OF_W0C+128+ch],lagv,xg[128+ch]);
        float go=gp[192+ch] +fmaf(sm[OF_W0C+192+ch],lagv,xg[192+ch]);
        float c=sigf(gf)*c0v[j]+sigf(gi)*tanhf_(gg);
        c0v[j]=c;
        hn[j]=sigf(go)*tanhf_(c);
      }
      __half2* h0p=(__half2*)&smu[OF_H0+r*HS+(ch0>>1)];
      #pragma unroll
      for(int j=0;j<4;j++)h0p[j]=__floats2half2_rn(hn[2*j],hn[2*j+1]);
    }
    __syncthreads();
    // phase 3: L1 MMA
    #pragma unroll
    for(int nt=0;nt<8;nt++){
      float d[4]={0,0,0,0};
      #pragma unroll
      for(int kt=0;kt<4;kt++){
        uint32_t b0r=smu[OF_H0+(nt*8+la)*HS+kt*8+lb];
        uint32_t b1r=smu[OF_H0+(nt*8+la)*HS+kt*8+lb+4];
        MMA(d,aI1[kt],b0r,b1r);
      }
      #pragma unroll
      for(int kt=0;kt<4;kt++){
        uint32_t b0r=smu[OF_H1+(nt*8+la)*HS+kt*8+lb];
        uint32_t b1r=smu[OF_H1+(nt*8+la)*HS+kt*8+lb+4];
        MMA(d,aH1[kt],b0r,b1r);
      }
      int n0=nt*8+lb*2,m=w*16+la;
      sm[OF_GATE+n0*GS+m]=d[0];     sm[OF_GATE+(n0+1)*GS+m]=d[1];
      sm[OF_GATE+n0*GS+m+8]=d[2];   sm[OF_GATE+(n0+1)*GS+m+8]=d[3];
    }
    __syncthreads();
    // phase 4: L1 update + projection partials + stage xproj t+1
    {
      const float* gp=&sm[OF_GATE+r*GS];
      float hn[8],p0=0.f,p1=0.f;
      #pragma unroll
      for(int j=0;j<8;j++){
        int ch=ch0+j;
        float gi=gp[ch]+sm[OF_BL1+ch];
        float gf=gp[64+ch]+sm[OF_BL1+64+ch];
        float gg=gp[128+ch]+sm[OF_BL1+128+ch];
        float go=gp[192+ch]+sm[OF_BL1+192+ch];
        float c=sigf(gf)*c1v[j]+sigf(gi)*tanhf_(gg);
        c1v[j]=c;
        float h=sigf(go)*tanhf_(c);
        hn[j]=h;
        p0=fmaf(sm[OF_WP+ch],h,p0);
        p1=fmaf(sm[OF_WP+64+ch],h,p1);
      }
      __half2* h1p=(__half2*)&smu[OF_H1+r*HS+(ch0>>1)];
      #pragma unroll
      for(int j=0;j<4;j++)h1p[j]=__floats2half2_rn(hn[2*j],hn[2*j+1]);
      sm[OF_RED+tid]=p0;
      sm[OF_RED+512+tid]=p1;
    }
    if(t+1<T_&&tid<512){
      int sel=tid>>8,g=tid&255;
      sm[OF_XG+(((t+1)&1)*2+sel)*256+g]=g_xproj[((sel?bL:b0)*T_+t+1)*G_+g];
    }
    __syncthreads();
  }
  if(tid<64){
    float r0=bp0,r1=bp1;
    #pragma unroll
    for(int k=0;k<8;k++){r0+=sm[OF_RED+k*64+tid];r1+=sm[OF_RED+512+k*64+tid];}
    float loc=fmaf(r0,scl,cen);
    float sig=softplusf_(r1)*scl;
    float pred=fmaf(sig,g_eps[(T_-1)*ROWS_TOTAL+gr0+tid],loc);
    out[(sb*T_+(T_-1))*NS_+ss]=pred;
  }
}

extern "C" void kernel_launch(void* const* d_in,const int* in_sizes,int n_in,
                              void* d_out,int out_size){
  (void)in_sizes;(void)n_in;(void)out_size;
  const float* dec_cont=(const float*)d_in[0];
  const float* one_off =(const float*)d_in[1];
  const float* ts      =(const float*)d_in[2];
  const float* emb0    =(const float*)d_in[3];
  const float* emb1    =(const float*)d_in[4];
  const float* Wih0    =(const float*)d_in[5];
  const float* Whh0    =(const float*)d_in[6];
  const float* bih0    =(const float*)d_in[7];
  const float* bhh0    =(const float*)d_in[8];
  const float* Wih1    =(const float*)d_in[9];
  const float* Whh1    =(const float*)d_in[10];
  const float* bih1    =(const float*)d_in[11];
  const float* bhh1    =(const float*)d_in[12];
  const float* Wproj   =(const float*)d_in[13];
  const float* bproj   =(const float*)d_in[14];
  const float* h0in    =(const float*)d_in[15];
  const float* c0in    =(const float*)d_in[16];
  const int*   dec_cat =(const int*)d_in[17];
  float* out=(float*)d_out;

  setup_kernel<<<4096+(T_*ROWS_TOTAL+255)/256,256>>>(dec_cont,emb0,emb1,Wih0,bih0,bhh0,dec_cat);

  cudaFuncSetAttribute(deepar_mma,cudaFuncAttributeMaxDynamicSharedMemorySize,SM_WORDS*4);
  deepar_mma<<<NCTA,TPB,SM_WORDS*4>>>(ts,one_off,Wih0,Whh0,Wih1,Whh1,
                                      bih1,bhh1,Wproj,bproj,h0in,c0in,out);
}

// round 11
// speedup vs baseline: 1.3253x; 1.3253x over previous
#include <cuda_runtime.h>
#include <cuda_fp16.h>
#include <cstdint>

#define B_ 128
#define T_ 32
#define NS_ 200
#define ROWS_TOTAL 25600
#define G_ 256
#define RPC 64
#define NCTA 400
#define TPB 512
#define GS 260
#define HS 36
#define OF_GATE 0
#define OF_H0 16640
#define OF_H1 18944
#define OF_XG 21248
#define OF_W0C 22272
#define OF_BL1 22528
#define OF_WP 22784
#define OF_LAG 22912
#define OF_RED 22976
#define SM_WORDS 24000

__device__ float g_xproj[B_*T_*G_];
__device__ float g_eps[T_*ROWS_TOTAL];

__device__ __forceinline__ uint32_t rotl32(uint32_t x,int d){return (x<<d)|(x>>(32-d));}
__device__ __forceinline__ float tanha(float x){float r;asm("tanh.approx.f32 %0, %1;":"=f"(r):"f"(x));return r;}
__device__ __forceinline__ float sigf(float x){return fmaf(tanha(0.5f*x),0.5f,0.5f);}
__device__ __forceinline__ float softplusf_(float x){return fmaxf(x,0.0f)+log1pf(expf(-fabsf(x)));}

__device__ __forceinline__ float erfinv_xla(float x){
  float w=-log1pf(-x*x),p;
  if(w<5.0f){w=w-2.5f;
    p=2.81022636e-08f;p=fmaf(p,w,3.43273939e-07f);p=fmaf(p,w,-3.5233877e-06f);
    p=fmaf(p,w,-4.39150654e-06f);p=fmaf(p,w,0.00021858087f);p=fmaf(p,w,-0.00125372503f);
    p=fmaf(p,w,-0.00417768164f);p=fmaf(p,w,0.246640727f);p=fmaf(p,w,1.50140941f);
  }else{w=sqrtf(w)-3.0f;
    p=-0.000200214257f;p=fmaf(p,w,0.000100950558f);p=fmaf(p,w,0.00134934322f);
    p=fmaf(p,w,-0.00367342844f);p=fmaf(p,w,0.00573950773f);p=fmaf(p,w,-0.0076224613f);
    p=fmaf(p,w,0.00943887047f);p=fmaf(p,w,1.00167406f);p=fmaf(p,w,2.83297682f);}
  return p*x;
}
__device__ __forceinline__ float bits_to_normal(uint32_t bits){
  float u=__uint_as_float((bits>>9)|0x3f800000u)-1.0f;
  float x=fmaf(u,2.0f,-0.99999994f);
  x=fmaxf(-0.99999994f,x);
  return 1.41421356f*erfinv_xla(x);
}

__global__ void setup_kernel(const float* __restrict__ dec_cont,const float* __restrict__ emb0,
    const float* __restrict__ emb1,const float* __restrict__ Wih0,const float* __restrict__ bih0,
    const float* __restrict__ bhh0,const int* __restrict__ dec_cat){
  if(blockIdx.x>=4096){
    uint32_t j=(blockIdx.x-4096)*blockDim.x+threadIdx.x;
    if(j>=(uint32_t)(T_*ROWS_TOTAL))return;
    const uint32_t ks0=0u,ks1=42u,ks2=0x1BD11BDAu^42u;
    uint32_t x0=0u,x1=j;
    x0+=ks0;x1+=ks1;
#define RND_(r){x0+=x1;x1=rotl32(x1,(r));x1^=x0;}
    RND_(13)RND_(15)RND_(26)RND_(6)  x0+=ks1;x1+=ks2+1u;
    RND_(17)RND_(29)RND_(16)RND_(24) x0+=ks2;x1+=ks0+2u;
    RND_(13)RND_(15)RND_(26)RND_(6)  x0+=ks0;x1+=ks1+3u;
    RND_(17)RND_(29)RND_(16)RND_(24) x0+=ks1;x1+=ks2+4u;
    RND_(13)RND_(15)RND_(26)RND_(6)  x0+=ks2;x1+=ks0+5u;
#undef RND_
    g_eps[j]=bits_to_normal(x0^x1);
    return;
  }
  int bt=blockIdx.x,g=threadIdx.x;
  __shared__ float feat[32];
  if(g<32){
    float v=0.0f;
    if(g>=1&&g<6)v=dec_cont[bt*6+g];
    else if(g>=6&&g<16)v=emb0[dec_cat[bt*2]*10+(g-6)];
    else if(g>=16)v=emb1[dec_cat[bt*2+1]*16+(g-16)];
    feat[g]=v;
  }
  __syncthreads();
  float acc=bih0[g]+bhh0[g];
  #pragma unroll
  for(int k=1;k<32;k++)acc=fmaf(Wih0[g*32+k],feat[k],acc);
  g_xproj[bt*G_+g]=acc;
}

#define MMA(d,a,bb0,bb1) \
  asm volatile("mma.sync.aligned.m16n8k16.row.col.f32.f16.f16.f32 " \
    "{%0,%1,%2,%3}, {%4,%5,%6,%7}, {%8,%9}, {%0,%1,%2,%3};" \
    : "+f"((d)[0]),"+f"((d)[1]),"+f"((d)[2]),"+f"((d)[3]) \
    : "r"((a)[0]),"r"((a)[1]),"r"((a)[2]),"r"((a)[3]),"r"(bb0),"r"(bb1))
#define LDM4(r0,r1,r2,r3,a) \
  asm volatile("ldmatrix.sync.aligned.m8n8.x4.shared.b16 {%0,%1,%2,%3},[%4];" \
    : "=r"(r0),"=r"(r1),"=r"(r2),"=r"(r3) : "r"(a))

__device__ __forceinline__ uint32_t f2h2(float lo,float hi){
  __half2 h=__floats2half2_rn(lo,hi);
  return *reinterpret_cast<uint32_t*>(&h);
}

__global__ __launch_bounds__(TPB,1)
void deepar_mma(const float* __restrict__ ts,const float* __restrict__ one_off,
    const float* __restrict__ Wih0,const float* __restrict__ Whh0,
    const float* __restrict__ Wih1,const float* __restrict__ Whh1,
    const float* __restrict__ bih1,const float* __restrict__ bhh1,
    const float* __restrict__ Wproj,const float* __restrict__ bproj,
    const float* __restrict__ h0in,const float* __restrict__ c0in,
    float* __restrict__ out)
{
  extern __shared__ float sm[];
  uint32_t* smu=(uint32_t*)sm;
  uint32_t smb4;
  asm("{.reg .u64 t; cvta.to.shared.u64 t,%1; cvt.u32.u64 %0,t;}":"=r"(smb4):"l"(sm));
  const int tid=threadIdx.x;
  const int w=tid>>5,lane=tid&31;
  const int la=lane>>2,lb=lane&3;
  const int gr0=blockIdx.x*RPC;
  const int b0=gr0/NS_,bL=(gr0+RPC-1)/NS_;
  const int r=tid&63,cb=tid>>6,ch0=cb*8;
  const int myb=(gr0+r)/NS_;
  const int bsel=(myb!=b0)?1:0;
  // ldmatrix per-thread address offsets
  const uint32_t bof=(uint32_t)((lane&7)*HS+(lane>>3)*4)*4u;
  const uint32_t h0b=smb4+OF_H0*4+bof, h1b=smb4+OF_H1*4+bof;

  uint32_t aW0[4][4],aI1[4][4],aH1[4][4];
  #pragma unroll
  for(int kt=0;kt<4;kt++){
    int m=w*16+la,k=kt*16+lb*2;
    aW0[kt][0]=f2h2(Whh0[m*64+k],Whh0[m*64+k+1]);
    aW0[kt][1]=f2h2(Whh0[(m+8)*64+k],Whh0[(m+8)*64+k+1]);
    aW0[kt][2]=f2h2(Whh0[m*64+k+8],Whh0[m*64+k+9]);
    aW0[kt][3]=f2h2(Whh0[(m+8)*64+k+8],Whh0[(m+8)*64+k+9]);
    aI1[kt][0]=f2h2(Wih1[m*64+k],Wih1[m*64+k+1]);
    aI1[kt][1]=f2h2(Wih1[(m+8)*64+k],Wih1[(m+8)*64+k+1]);
    aI1[kt][2]=f2h2(Wih1[m*64+k+8],Wih1[m*64+k+9]);
    aI1[kt][3]=f2h2(Wih1[(m+8)*64+k+8],Wih1[(m+8)*64+k+9]);
    aH1[kt][0]=f2h2(Whh1[m*64+k],Whh1[m*64+k+1]);
    aH1[kt][1]=f2h2(Whh1[(m+8)*64+k],Whh1[(m+8)*64+k+1]);
    aH1[kt][2]=f2h2(Whh1[m*64+k+8],Whh1[m*64+k+9]);
    aH1[kt][3]=f2h2(Whh1[(m+8)*64+k+8],Whh1[(m+8)*64+k+9]);
  }

  if(tid<256){
    sm[OF_W0C+tid]=Wih0[tid*32];
    sm[OF_BL1+tid]=bih1[tid]+bhh1[tid];
  }
  if(tid<128)sm[OF_WP+tid]=Wproj[tid];
  if(tid<64)sm[OF_LAG+tid]=one_off[(gr0+tid)/NS_];
  {
    int sel=tid>>8,g=tid&255;
    sm[OF_XG+sel*256+g]=g_xproj[((sel?bL:b0)*T_)*G_+g];
  }
  float c0v[8],c1v[8];
  {
    #pragma unroll
    for(int j=0;j<8;j++){
      int ch=ch0+j;
      c0v[j]=c0in[myb*64+ch];
      c1v[j]=c0in[8192+myb*64+ch];
    }
    uint32_t hw0[4],hw1[4];
    #pragma unroll
    for(int j=0;j<4;j++){
      int ch=ch0+2*j;
      hw0[j]=f2h2(h0in[myb*64+ch],h0in[myb*64+ch+1]);
      hw1[j]=f2h2(h0in[8192+myb*64+ch],h0in[8192+myb*64+ch+1]);
    }
    *(uint4*)&smu[OF_H0+r*HS+(ch0>>1)]=*(uint4*)hw0;
    *(uint4*)&smu[OF_H1+r*HS+(ch0>>1)]=*(uint4*)hw1;
  }
  float cen=0.f,scl=1.f,bp0=0.f,bp1=0.f;
  int sb=0,ss=0;
  if(tid<64){
    int sgr=gr0+tid;
    sb=sgr/NS_;ss=sgr-sb*NS_;
    cen=ts[2*sb];scl=ts[2*sb+1];
    bp0=bproj[0];bp1=bproj[1];
  }
  __syncthreads();

  #pragma unroll 1
  for(int t=0;t<T_;t++){
    // phase 1: L0 MMA (+ finalize sample t-1)
    #pragma unroll
    for(int nt=0;nt<8;nt++){
      uint32_t b[8];
      uint32_t a0=h0b+(uint32_t)(nt*8*HS*4);
      LDM4(b[0],b[1],b[2],b[3],a0);
      LDM4(b[4],b[5],b[6],b[7],a0+64u);
      float d[4]={0,0,0,0};
      MMA(d,aW0[0],b[0],b[1]);MMA(d,aW0[1],b[2],b[3]);
      MMA(d,aW0[2],b[4],b[5]);MMA(d,aW0[3],b[6],b[7]);
      int n0=nt*8+lb*2,m=w*16+la;
      sm[OF_GATE+n0*GS+m]=d[0];     sm[OF_GATE+(n0+1)*GS+m]=d[1];
      sm[OF_GATE+n0*GS+m+8]=d[2];   sm[OF_GATE+(n0+1)*GS+m+8]=d[3];
    }
    if(t>0&&tid<64){
      int tp=t-1;
      float r0=bp0,r1=bp1;
      #pragma unroll
      for(int k=0;k<8;k++){r0+=sm[OF_RED+k*64+tid];r1+=sm[OF_RED+512+k*64+tid];}
      float loc=fmaf(r0,scl,cen);
      float sig=softplusf_(r1)*scl;
      float pred=fmaf(sig,g_eps[tp*ROWS_TOTAL+gr0+tid],loc);
      out[(sb*T_+tp)*NS_+ss]=pred;
      sm[OF_LAG+tid]=(pred-cen)/scl;
    }
    __syncthreads();
    // phase 2: L0 update
    {
      const float lagv=sm[OF_LAG+r];
      const float* gp=&sm[OF_GATE+r*GS];
      const float* xg=&sm[OF_XG+((t&1)*2+bsel)*256];
      float gi[8],gf[8],gg[8],go[8];
      #pragma unroll
      for(int q=0;q<2;q++){
        float4 A,X,W;
        A=*(const float4*)&gp[ch0+q*4];X=*(const float4*)&xg[ch0+q*4];W=*(const float4*)&sm[OF_W0C+ch0+q*4];
        gi[q*4+0]=A.x+fmaf(W.x,lagv,X.x);gi[q*4+1]=A.y+fmaf(W.y,lagv,X.y);
        gi[q*4+2]=A.z+fmaf(W.z,lagv,X.z);gi[q*4+3]=A.w+fmaf(W.w,lagv,X.w);
        A=*(const float4*)&gp[64+ch0+q*4];X=*(const float4*)&xg[64+ch0+q*4];W=*(const float4*)&sm[OF_W0C+64+ch0+q*4];
        gf[q*4+0]=A.x+fmaf(W.x,lagv,X.x);gf[q*4+1]=A.y+fmaf(W.y,lagv,X.y);
        gf[q*4+2]=A.z+fmaf(W.z,lagv,X.z);gf[q*4+3]=A.w+fmaf(W.w,lagv,X.w);
        A=*(const float4*)&gp[128+ch0+q*4];X=*(const float4*)&xg[128+ch0+q*4];W=*(const float4*)&sm[OF_W0C+128+ch0+q*4];
        gg[q*4+0]=A.x+fmaf(W.x,lagv,X.x);gg[q*4+1]=A.y+fmaf(W.y,lagv,X.y);
        gg[q*4+2]=A.z+fmaf(W.z,lagv,X.z);gg[q*4+3]=A.w+fmaf(W.w,lagv,X.w);
        A=*(const float4*)&gp[192+ch0+q*4];X=*(const float4*)&xg[192+ch0+q*4];W=*(const float4*)&sm[OF_W0C+192+ch0+q*4];
        go[q*4+0]=A.x+fmaf(W.x,lagv,X.x);go[q*4+1]=A.y+fmaf(W.y,lagv,X.y);
        go[q*4+2]=A.z+fmaf(W.z,lagv,X.z);go[q*4+3]=A.w+fmaf(W.w,lagv,X.w);
      }
      float hn[8];
      #pragma unroll
      for(int j=0;j<8;j++){
        float c=sigf(gf[j])*c0v[j]+sigf(gi[j])*tanha(gg[j]);
        c0v[j]=c;
        hn[j]=sigf(go[j])*tanha(c);
      }
      uint32_t hw[4];
      #pragma unroll
      for(int j=0;j<4;j++)hw[j]=f2h2(hn[2*j],hn[2*j+1]);
      *(uint4*)&smu[OF_H0+r*HS+(ch0>>1)]=*(uint4*)hw;
    }
    __syncthreads();
    // phase 3: L1 MMA
    #pragma unroll
    for(int nt=0;nt<8;nt++){
      uint32_t b[8],b2[8];
      uint32_t a0=h0b+(uint32_t)(nt*8*HS*4);
      uint32_t a1=h1b+(uint32_t)(nt*8*HS*4);
      LDM4(b[0],b[1],b[2],b[3],a0);
      LDM4(b[4],b[5],b[6],b[7],a0+64u);
      LDM4(b2[0],b2[1],b2[2],b2[3],a1);
      LDM4(b2[4],b2[5],b2[6],b2[7],a1+64u);
      float d[4]={0,0,0,0};
      MMA(d,aI1[0],b[0],b[1]);MMA(d,aI1[1],b[2],b[3]);
      MMA(d,aI1[2],b[4],b[5]);MMA(d,aI1[3],b[6],b[7]);
      MMA(d,aH1[0],b2[0],b2[1]);MMA(d,aH1[1],b2[2],b2[3]);
      MMA(d,aH1[2],b2[4],b2[5]);MMA(d,aH1[3],b2[6],b2[7]);
      int n0=nt*8+lb*2,m=w*16+la;
      sm[OF_GATE+n0*GS+m]=d[0];     sm[OF_GATE+(n0+1)*GS+m]=d[1];
      sm[OF_GATE+n0*GS+m+8]=d[2];   sm[OF_GATE+(n0+1)*GS+m+8]=d[3];
    }
    __syncthreads();
    // phase 4: L1 update + projection partials + stage xproj t+1
    {
      const float* gp=&sm[OF_GATE+r*GS];
      float gi[8],gf[8],gg[8],go[8];
      #pragma unroll
      for(int q=0;q<2;q++){
        float4 A,Bv;
        A=*(const float4*)&gp[ch0+q*4];Bv=*(const float4*)&sm[OF_BL1+ch0+q*4];
        gi[q*4+0]=A.x+Bv.x;gi[q*4+1]=A.y+Bv.y;gi[q*4+2]=A.z+Bv.z;gi[q*4+3]=A.w+Bv.w;
        A=*(const float4*)&gp[64+ch0+q*4];Bv=*(const float4*)&sm[OF_BL1+64+ch0+q*4];
        gf[q*4+0]=A.x+Bv.x;gf[q*4+1]=A.y+Bv.y;gf[q*4+2]=A.z+Bv.z;gf[q*4+3]=A.w+Bv.w;
        A=*(const float4*)&gp[128+ch0+q*4];Bv=*(const float4*)&sm[OF_BL1+128+ch0+q*4];
        gg[q*4+0]=A.x+Bv.x;gg[q*4+1]=A.y+Bv.y;gg[q*4+2]=A.z+Bv.z;gg[q*4+3]=A.w+Bv.w;
        A=*(const float4*)&gp[192+ch0+q*4];Bv=*(const float4*)&sm[OF_BL1+192+ch0+q*4];
        go[q*4+0]=A.x+Bv.x;go[q*4+1]=A.y+Bv.y;go[q*4+2]=A.z+Bv.z;go[q*4+3]=A.w+Bv.w;
      }
      float hn[8],p0=0.f,p1=0.f;
      #pragma unroll
      for(int j=0;j<8;j++){
        float c=sigf(gf[j])*c1v[j]+sigf(gi[j])*tanha(gg[j]);
        c1v[j]=c;
        hn[j]=sigf(go[j])*tanha(c);
      }
      #pragma unroll
      for(int q=0;q<2;q++){
        float4 W0=*(const float4*)&sm[OF_WP+ch0+q*4];
        float4 W1=*(const float4*)&sm[OF_WP+64+ch0+q*4];
        p0=fmaf(W0.x,hn[q*4+0],p0);p0=fmaf(W0.y,hn[q*4+1],p0);
        p0=fmaf(W0.z,hn[q*4+2],p0);p0=fmaf(W0.w,hn[q*4+3],p0);
        p1=fmaf(W1.x,hn[q*4+0],p1);p1=fmaf(W1.y,hn[q*4+1],p1);
        p1=fmaf(W1.z,hn[q*4+2],p1);p1=fmaf(W1.w,hn[q*4+3],p1);
      }
      uint32_t hw[4];
      #pragma unroll
      for(int j=0;j<4;j++)hw[j]=f2h2(hn[2*j],hn[2*j+1]);
      *(uint4*)&smu[OF_H1+r*HS+(ch0>>1)]=*(uint4*)hw;
      sm[OF_RED+tid]=p0;
      sm[OF_RED+512+tid]=p1;
    }
    if(t+1<T_){
      int sel=tid>>8,g=tid&255;
      sm[OF_XG+(((t+1)&1)*2+sel)*256+g]=g_xproj[((sel?bL:b0)*T_+t+1)*G_+g];
    }
    __syncthreads();
  }
  if(tid<64){
    float r0=bp0,r1=bp1;
    #pragma unroll
    for(int k=0;k<8;k++){r0+=sm[OF_RED+k*64+tid];r1+=sm[OF_RED+512+k*64+tid];}
    float loc=fmaf(r0,scl,cen);
    float sig=softplusf_(r1)*scl;
    float pred=fmaf(sig,g_eps[(T_-1)*ROWS_TOTAL+gr0+tid],loc);
    out[(sb*T_+(T_-1))*NS_+ss]=pred;
  }
}

extern "C" void kernel_launch(void* const* d_in,const int* in_sizes,int n_in,
                              void* d_out,int out_size){
  (void)in_sizes;(void)n_in;(void)out_size;
  const float* dec_cont=(const float*)d_in[0];
  const float* one_off =(const float*)d_in[1];
  const float* ts      =(const float*)d_in[2];
  const float* emb0    =(const float*)d_in[3];
  const float* emb1    =(const float*)d_in[4];
  const float* Wih0    =(const float*)d_in[5];
  const float* Whh0    =(const float*)d_in[6];
  const float* bih0    =(const float*)d_in[7];
  const float* bhh0    =(const float*)d_in[8];
  const float* Wih1    =(const float*)d_in[9];
  const float* Whh1    =(const float*)d_in[10];
  const float* bih1    =(const float*)d_in[11];
  const float* bhh1    =(const float*)d_in[12];
  const float* Wproj   =(const float*)d_in[13];
  const float* bproj   =(const float*)d_in[14];
  const float* h0in    =(const float*)d_in[15];
  const float* c0in    =(const float*)d_in[16];
  const int*   dec_cat =(const int*)d_in[17];
  float* out=(float*)d_out;

  setup_kernel<<<4096+(T_*ROWS_TOTAL+255)/256,256>>>(dec_cont,emb0,emb1,Wih0,bih0,bhh0,dec_cat);

  cudaFuncSetAttribute(deepar_mma,cudaFuncAttributeMaxDynamicSharedMemorySize,SM_WORDS*4);
  deepar_mma<<<NCTA,TPB,SM_WORDS*4>>>(ts,one_off,Wih0,Whh0,Wih1,Whh1,
                                      bih1,bhh1,Wproj,bproj,h0in,c0in,out);
}

// round 13
// speedup vs baseline: 1.4055x; 1.0605x over previous
#include <cuda_runtime.h>
#include <cuda_fp16.h>
#include <cstdint>

#define B_ 128
#define T_ 32
#define NS_ 200
#define ROWS_TOTAL 25600
#define G_ 256
#define RPC 64
#define NCTA 400
#define TPB 256
#define GS 260
#define HS 36
#define OF_GATE 0
#define OF_H0 16640
#define OF_H1 18944
#define OF_XG 21248
#define OF_W0C 22272
#define OF_BL1 22528
#define OF_WP 22784
#define OF_LAG 22912
#define OF_RED 22976
#define SM_WORDS 24000

__device__ float g_xproj[B_*T_*G_];
__device__ float g_eps[T_*ROWS_TOTAL];

__device__ __forceinline__ uint32_t rotl32(uint32_t x,int d){return (x<<d)|(x>>(32-d));}
__device__ __forceinline__ float tanha(float x){float r;asm("tanh.approx.f32 %0, %1;":"=f"(r):"f"(x));return r;}
__device__ __forceinline__ float sigf(float x){return fmaf(tanha(0.5f*x),0.5f,0.5f);}
__device__ __forceinline__ float softplusf_(float x){return fmaxf(x,0.0f)+log1pf(expf(-fabsf(x)));}

__device__ __forceinline__ float erfinv_xla(float x){
  float w=-log1pf(-x*x),p;
  if(w<5.0f){w=w-2.5f;
    p=2.81022636e-08f;p=fmaf(p,w,3.43273939e-07f);p=fmaf(p,w,-3.5233877e-06f);
    p=fmaf(p,w,-4.39150654e-06f);p=fmaf(p,w,0.00021858087f);p=fmaf(p,w,-0.00125372503f);
    p=fmaf(p,w,-0.00417768164f);p=fmaf(p,w,0.246640727f);p=fmaf(p,w,1.50140941f);
  }else{w=sqrtf(w)-3.0f;
    p=-0.000200214257f;p=fmaf(p,w,0.000100950558f);p=fmaf(p,w,0.00134934322f);
    p=fmaf(p,w,-0.00367342844f);p=fmaf(p,w,0.00573950773f);p=fmaf(p,w,-0.0076224613f);
    p=fmaf(p,w,0.00943887047f);p=fmaf(p,w,1.00167406f);p=fmaf(p,w,2.83297682f);}
  return p*x;
}
__device__ __forceinline__ float bits_to_normal(uint32_t bits){
  float u=__uint_as_float((bits>>9)|0x3f800000u)-1.0f;
  float x=fmaf(u,2.0f,-0.99999994f);
  x=fmaxf(-0.99999994f,x);
  return 1.41421356f*erfinv_xla(x);
}

__global__ void setup_kernel(const float* __restrict__ dec_cont,const float* __restrict__ emb0,
    const float* __restrict__ emb1,const float* __restrict__ Wih0,const float* __restrict__ bih0,
    const float* __restrict__ bhh0,const int* __restrict__ dec_cat){
  if(blockIdx.x>=4096){
    uint32_t j=(blockIdx.x-4096)*blockDim.x+threadIdx.x;
    if(j>=(uint32_t)(T_*ROWS_TOTAL))return;
    const uint32_t ks0=0u,ks1=42u,ks2=0x1BD11BDAu^42u;
    uint32_t x0=0u,x1=j;
    x0+=ks0;x1+=ks1;
#define RND_(r){x0+=x1;x1=rotl32(x1,(r));x1^=x0;}
    RND_(13)RND_(15)RND_(26)RND_(6)  x0+=ks1;x1+=ks2+1u;
    RND_(17)RND_(29)RND_(16)RND_(24) x0+=ks2;x1+=ks0+2u;
    RND_(13)RND_(15)RND_(26)RND_(6)  x0+=ks0;x1+=ks1+3u;
    RND_(17)RND_(29)RND_(16)RND_(24) x0+=ks1;x1+=ks2+4u;
    RND_(13)RND_(15)RND_(26)RND_(6)  x0+=ks2;x1+=ks0+5u;
#undef RND_
    g_eps[j]=bits_to_normal(x0^x1);
    return;
  }
  int bt=blockIdx.x,g=threadIdx.x;
  __shared__ float feat[32];
  if(g<32){
    float v=0.0f;
    if(g>=1&&g<6)v=dec_cont[bt*6+g];
    else if(g>=6&&g<16)v=emb0[dec_cat[bt*2]*10+(g-6)];
    else if(g>=16)v=emb1[dec_cat[bt*2+1]*16+(g-16)];
    feat[g]=v;
  }
  __syncthreads();
  float acc=bih0[g]+bhh0[g];
  #pragma unroll
  for(int k=1;k<32;k++)acc=fmaf(Wih0[g*32+k],feat[k],acc);
  g_xproj[bt*G_+g]=acc;
}

#define MMA(d,a,bb0,bb1) \
  asm volatile("mma.sync.aligned.m16n8k16.row.col.f32.f16.f16.f32 " \
    "{%0,%1,%2,%3}, {%4,%5,%6,%7}, {%8,%9}, {%0,%1,%2,%3};" \
    : "+f"((d)[0]),"+f"((d)[1]),"+f"((d)[2]),"+f"((d)[3]) \
    : "r"((a)[0]),"r"((a)[1]),"r"((a)[2]),"r"((a)[3]),"r"(bb0),"r"(bb1))
#define LDM4(r0,r1,r2,r3,a) \
  asm volatile("ldmatrix.sync.aligned.m8n8.x4.shared.b16 {%0,%1,%2,%3},[%4];" \
    : "=r"(r0),"=r"(r1),"=r"(r2),"=r"(r3) : "r"(a))

__device__ __forceinline__ uint32_t f2h2(float lo,float hi){
  __half2 h=__floats2half2_rn(lo,hi);
  return *reinterpret_cast<uint32_t*>(&h);
}

__global__ __launch_bounds__(TPB,1)
void deepar_mma(const float* __restrict__ ts,const float* __restrict__ one_off,
    const float* __restrict__ Wih0,const float* __restrict__ Whh0,
    const float* __restrict__ Wih1,const float* __restrict__ Whh1,
    const float* __restrict__ bih1,const float* __restrict__ bhh1,
    const float* __restrict__ Wproj,const float* __restrict__ bproj,
    const float* __restrict__ h0in,const float* __restrict__ c0in,
    float* __restrict__ out)
{
  extern __shared__ float sm[];
  uint32_t* smu=(uint32_t*)sm;
  uint32_t smb4;
  asm("{.reg .u64 t; cvta.to.shared.u64 t,%1; cvt.u32.u64 %0,t;}":"=r"(smb4):"l"(sm));
  const int tid=threadIdx.x;
  const int w=tid>>5,lane=tid&31;
  const int la=lane>>2,lb=lane&3;
  const int gr0=blockIdx.x*RPC;
  const int b0=gr0/NS_,bL=(gr0+RPC-1)/NS_;
  const int r=tid&63,cb=tid>>6,ch0=cb*16;
  const int myb=(gr0+r)/NS_;
  const int bsel=(myb!=b0)?1:0;
  const uint32_t bof=(uint32_t)((lane&7)*HS+(lane>>3)*4)*4u;
  const uint32_t h0b=smb4+OF_H0*4+bof, h1b=smb4+OF_H1*4+bof;

  uint32_t aW0[2][4][4],aI1[2][4][4],aH1[2][4][4];
  #pragma unroll
  for(int mt=0;mt<2;mt++){
    #pragma unroll
    for(int kt=0;kt<4;kt++){
      int m=w*32+mt*16+la,k=kt*16+lb*2;
      aW0[mt][kt][0]=f2h2(Whh0[m*64+k],Whh0[m*64+k+1]);
      aW0[mt][kt][1]=f2h2(Whh0[(m+8)*64+k],Whh0[(m+8)*64+k+1]);
      aW0[mt][kt][2]=f2h2(Whh0[m*64+k+8],Whh0[m*64+k+9]);
      aW0[mt][kt][3]=f2h2(Whh0[(m+8)*64+k+8],Whh0[(m+8)*64+k+9]);
      aI1[mt][kt][0]=f2h2(Wih1[m*64+k],Wih1[m*64+k+1]);
      aI1[mt][kt][1]=f2h2(Wih1[(m+8)*64+k],Wih1[(m+8)*64+k+1]);
      aI1[mt][kt][2]=f2h2(Wih1[m*64+k+8],Wih1[m*64+k+9]);
      aI1[mt][kt][3]=f2h2(Wih1[(m+8)*64+k+8],Wih1[(m+8)*64+k+9]);
      aH1[mt][kt][0]=f2h2(Whh1[m*64+k],Whh1[m*64+k+1]);
      aH1[mt][kt][1]=f2h2(Whh1[(m+8)*64+k],Whh1[(m+8)*64+k+1]);
      aH1[mt][kt][2]=f2h2(Whh1[m*64+k+8],Whh1[m*64+k+9]);
      aH1[mt][kt][3]=f2h2(Whh1[(m+8)*64+k+8],Whh1[(m+8)*64+k+9]);
    }
  }

  sm[OF_W0C+tid]=Wih0[tid*32];
  sm[OF_BL1+tid]=bih1[tid]+bhh1[tid];
  if(tid<128)sm[OF_WP+tid]=Wproj[tid];
  if(tid<64)sm[OF_LAG+tid]=one_off[(gr0+tid)/NS_];
  #pragma unroll
  for(int q=tid;q<512;q+=TPB){
    int sel=q>>8,g=q&255;
    sm[OF_XG+sel*256+g]=g_xproj[((sel?bL:b0)*T_)*G_+g];
  }
  float c0v[16],c1v[16];
  {
    #pragma unroll
    for(int j=0;j<16;j++){
      int ch=ch0+j;
      c0v[j]=c0in[myb*64+ch];
      c1v[j]=c0in[8192+myb*64+ch];
    }
    uint32_t hw0[8],hw1[8];
    #pragma unroll
    for(int j=0;j<8;j++){
      int ch=ch0+2*j;
      hw0[j]=f2h2(h0in[myb*64+ch],h0in[myb*64+ch+1]);
      hw1[j]=f2h2(h0in[8192+myb*64+ch],h0in[8192+myb*64+ch+1]);
    }
    *(uint4*)&smu[OF_H0+r*HS+(ch0>>1)]=*(uint4*)hw0;
    *(uint4*)&smu[OF_H0+r*HS+(ch0>>1)+4]=*(uint4*)(hw0+4);
    *(uint4*)&smu[OF_H1+r*HS+(ch0>>1)]=*(uint4*)hw1;
    *(uint4*)&smu[OF_H1+r*HS+(ch0>>1)+4]=*(uint4*)(hw1+4);
  }
  float cen=0.f,scl=1.f,bp0=0.f,bp1=0.f;
  int sb=0,ss=0;
  if(tid<64){
    int sgr=gr0+tid;
    sb=sgr/NS_;ss=sgr-sb*NS_;
    cen=ts[2*sb];scl=ts[2*sb+1];
    bp0=bproj[0];bp1=bproj[1];
  }
  __syncthreads();

  #pragma unroll 1
  for(int t=0;t<T_;t++){
    // phase 1: L0 MMA (+ finalize sample t-1)
    #pragma unroll
    for(int nt=0;nt<8;nt++){
      uint32_t b[8];
      uint32_t a0=h0b+(uint32_t)(nt*8*HS*4);
      LDM4(b[0],b[1],b[2],b[3],a0);
      LDM4(b[4],b[5],b[6],b[7],a0+64u);
      float d0[4]={0,0,0,0},d1[4]={0,0,0,0};
      MMA(d0,aW0[0][0],b[0],b[1]);MMA(d1,aW0[1][0],b[0],b[1]);
      MMA(d0,aW0[0][1],b[2],b[3]);MMA(d1,aW0[1][1],b[2],b[3]);
      MMA(d0,aW0[0][2],b[4],b[5]);MMA(d1,aW0[1][2],b[4],b[5]);
      MMA(d0,aW0[0][3],b[6],b[7]);MMA(d1,aW0[1][3],b[6],b[7]);
      int n0=nt*8+lb*2,m=w*32+la;
      sm[OF_GATE+n0*GS+m]=d0[0];      sm[OF_GATE+(n0+1)*GS+m]=d0[1];
      sm[OF_GATE+n0*GS+m+8]=d0[2];    sm[OF_GATE+(n0+1)*GS+m+8]=d0[3];
      sm[OF_GATE+n0*GS+m+16]=d1[0];   sm[OF_GATE+(n0+1)*GS+m+16]=d1[1];
      sm[OF_GATE+n0*GS+m+24]=d1[2];   sm[OF_GATE+(n0+1)*GS+m+24]=d1[3];
    }
    if(t>0&&tid<64){
      int tp=t-1;
      float r0=bp0,r1=bp1;
      #pragma unroll
      for(int k=0;k<4;k++){r0+=sm[OF_RED+k*64+tid];r1+=sm[OF_RED+256+k*64+tid];}
      float loc=fmaf(r0,scl,cen);
      float sig=softplusf_(r1)*scl;
      float pred=fmaf(sig,g_eps[tp*ROWS_TOTAL+gr0+tid],loc);
      out[(sb*T_+tp)*NS_+ss]=pred;
      sm[OF_LAG+tid]=(pred-cen)/scl;
    }
    __syncthreads();
    // phase 2: L0 update
    {
      const float lagv=sm[OF_LAG+r];
      const float* gp=&sm[OF_GATE+r*GS];
      const float* xg=&sm[OF_XG+((t&1)*2+bsel)*256];
      float gi[16],gf[16],gg[16],go[16];
      #pragma unroll
      for(int q=0;q<4;q++){
        float4 A,X,W;
        A=*(const float4*)&gp[ch0+q*4];X=*(const float4*)&xg[ch0+q*4];W=*(const float4*)&sm[OF_W0C+ch0+q*4];
        gi[q*4+0]=A.x+fmaf(W.x,lagv,X.x);gi[q*4+1]=A.y+fmaf(W.y,lagv,X.y);
        gi[q*4+2]=A.z+fmaf(W.z,lagv,X.z);gi[q*4+3]=A.w+fmaf(W.w,lagv,X.w);
        A=*(const float4*)&gp[64+ch0+q*4];X=*(const float4*)&xg[64+ch0+q*4];W=*(const float4*)&sm[OF_W0C+64+ch0+q*4];
        gf[q*4+0]=A.x+fmaf(W.x,lagv,X.x);gf[q*4+1]=A.y+fmaf(W.y,lagv,X.y);
        gf[q*4+2]=A.z+fmaf(W.z,lagv,X.z);gf[q*4+3]=A.w+fmaf(W.w,lagv,X.w);
        A=*(const float4*)&gp[128+ch0+q*4];X=*(const float4*)&xg[128+ch0+q*4];W=*(const float4*)&sm[OF_W0C+128+ch0+q*4];
        gg[q*4+0]=A.x+fmaf(W.x,lagv,X.x);gg[q*4+1]=A.y+fmaf(W.y,lagv,X.y);
        gg[q*4+2]=A.z+fmaf(W.z,lagv,X.z);gg[q*4+3]=A.w+fmaf(W.w,lagv,X.w);
        A=*(const float4*)&gp[192+ch0+q*4];X=*(const float4*)&xg[192+ch0+q*4];W=*(const float4*)&sm[OF_W0C+192+ch0+q*4];
        go[q*4+0]=A.x+fmaf(W.x,lagv,X.x);go[q*4+1]=A.y+fmaf(W.y,lagv,X.y);
        go[q*4+2]=A.z+fmaf(W.z,lagv,X.z);go[q*4+3]=A.w+fmaf(W.w,lagv,X.w);
      }
      float hn[16];
      #pragma unroll
      for(int j=0;j<16;j++){
        float c=sigf(gf[j])*c0v[j]+sigf(gi[j])*tanha(gg[j]);
        c0v[j]=c;
        hn[j]=sigf(go[j])*tanha(c);
      }
      uint32_t hw[8];
      #pragma unroll
      for(int j=0;j<8;j++)hw[j]=f2h2(hn[2*j],hn[2*j+1]);
      *(uint4*)&smu[OF_H0+r*HS+(ch0>>1)]=*(uint4*)hw;
      *(uint4*)&smu[OF_H0+r*HS+(ch0>>1)+4]=*(uint4*)(hw+4);
    }
    __syncthreads();
    // phase 3: L1 MMA
    #pragma unroll
    for(int nt=0;nt<8;nt++){
      uint32_t b[8],b2[8];
      uint32_t a0=h0b+(uint32_t)(nt*8*HS*4);
      uint32_t a1=h1b+(uint32_t)(nt*8*HS*4);
      LDM4(b[0],b[1],b[2],b[3],a0);
      LDM4(b[4],b[5],b[6],b[7],a0+64u);
      LDM4(b2[0],b2[1],b2[2],b2[3],a1);
      LDM4(b2[4],b2[5],b2[6],b2[7],a1+64u);
      float d0[4]={0,0,0,0},d1[4]={0,0,0,0};
      MMA(d0,aI1[0][0],b[0],b[1]);MMA(d1,aI1[1][0],b[0],b[1]);
      MMA(d0,aI1[0][1],b[2],b[3]);MMA(d1,aI1[1][1],b[2],b[3]);
      MMA(d0,aI1[0][2],b[4],b[5]);MMA(d1,aI1[1][2],b[4],b[5]);
      MMA(d0,aI1[0][3],b[6],b[7]);MMA(d1,aI1[1][3],b[6],b[7]);
      MMA(d0,aH1[0][0],b2[0],b2[1]);MMA(d1,aH1[1][0],b2[0],b2[1]);
      MMA(d0,aH1[0][1],b2[2],b2[3]);MMA(d1,aH1[1][1],b2[2],b2[3]);
      MMA(d0,aH1[0][2],b2[4],b2[5]);MMA(d1,aH1[1][2],b2[4],b2[5]);
      MMA(d0,aH1[0][3],b2[6],b2[7]);MMA(d1,aH1[1][3],b2[6],b2[7]);
      int n0=nt*8+lb*2,m=w*32+la;
      sm[OF_GATE+n0*GS+m]=d0[0];      sm[OF_GATE+(n0+1)*GS+m]=d0[1];
      sm[OF_GATE+n0*GS+m+8]=d0[2];    sm[OF_GATE+(n0+1)*GS+m+8]=d0[3];
      sm[OF_GATE+n0*GS+m+16]=d1[0];   sm[OF_GATE+(n0+1)*GS+m+16]=d1[1];
      sm[OF_GATE+n0*GS+m+24]=d1[2];   sm[OF_GATE+(n0+1)*GS+m+24]=d1[3];
    }
    __syncthreads();
    // phase 4: L1 update + projection partials + stage xproj t+1
    {
      const float* gp=&sm[OF_GATE+r*GS];
      float gi[16],gf[16],gg[16],go[16];
      #pragma unroll
      for(int q=0;q<4;q++){
        float4 A,Bv;
        A=*(const float4*)&gp[ch0+q*4];Bv=*(const float4*)&sm[OF_BL1+ch0+q*4];
        gi[q*4+0]=A.x+Bv.x;gi[q*4+1]=A.y+Bv.y;gi[q*4+2]=A.z+Bv.z;gi[q*4+3]=A.w+Bv.w;
        A=*(const float4*)&gp[64+ch0+q*4];Bv=*(const float4*)&sm[OF_BL1+64+ch0+q*4];
        gf[q*4+0]=A.x+Bv.x;gf[q*4+1]=A.y+Bv.y;gf[q*4+2]=A.z+Bv.z;gf[q*4+3]=A.w+Bv.w;
        A=*(const float4*)&gp[128+ch0+q*4];Bv=*(const float4*)&sm[OF_BL1+128+ch0+q*4];
        gg[q*4+0]=A.x+Bv.x;gg[q*4+1]=A.y+Bv.y;gg[q*4+2]=A.z+Bv.z;gg[q*4+3]=A.w+Bv.w;
        A=*(const float4*)&gp[192+ch0+q*4];Bv=*(const float4*)&sm[OF_BL1+192+ch0+q*4];
        go[q*4+0]=A.x+Bv.x;go[q*4+1]=A.y+Bv.y;go[q*4+2]=A.z+Bv.z;go[q*4+3]=A.w+Bv.w;
      }
      float hn[16],p0=0.f,p1=0.f;
      #pragma unroll
      for(int j=0;j<16;j++){
        float c=sigf(gf[j])*c1v[j]+sigf(gi[j])*tanha(gg[j]);
        c1v[j]=c;
        hn[j]=sigf(go[j])*tanha(c);
      }
      #pragma unroll
      for(int q=0;q<4;q++){
        float4 W0=*(const float4*)&sm[OF_WP+ch0+q*4];
        float4 W1=*(const float4*)&sm[OF_WP+64+ch0+q*4];
        p0=fmaf(W0.x,hn[q*4+0],p0);p0=fmaf(W0.y,hn[q*4+1],p0);
        p0=fmaf(W0.z,hn[q*4+2],p0);p0=fmaf(W0.w,hn[q*4+3],p0);
        p1=fmaf(W1.x,hn[q*4+0],p1);p1=fmaf(W1.y,hn[q*4+1],p1);
        p1=fmaf(W1.z,hn[q*4+2],p1);p1=fmaf(W1.w,hn[q*4+3],p1);
      }
      uint32_t hw[8];
      #pragma unroll
      for(int j=0;j<8;j++)hw[j]=f2h2(hn[2*j],hn[2*j+1]);
      *(uint4*)&smu[OF_H1+r*HS+(ch0>>1)]=*(uint4*)hw;
      *(uint4*)&smu[OF_H1+r*HS+(ch0>>1)+4]=*(uint4*)(hw+4);
      sm[OF_RED+tid]=p0;
      sm[OF_RED+256+tid]=p1;
    }
    if(t+1<T_){
      #pragma unroll
      for(int q=tid;q<512;q+=TPB){
        int sel=q>>8,g=q&255;
        sm[OF_XG+(((t+1)&1)*2+sel)*256+g]=g_xproj[((sel?bL:b0)*T_+t+1)*G_+g];
      }
    }
    __syncthreads();
  }
  if(tid<64){
    float r0=bp0,r1=bp1;
    #pragma unroll
    for(int k=0;k<4;k++){r0+=sm[OF_RED+k*64+tid];r1+=sm[OF_RED+256+k*64+tid];}
    float loc=fmaf(r0,scl,cen);
    float sig=softplusf_(r1)*scl;
    float pred=fmaf(sig,g_eps[(T_-1)*ROWS_TOTAL+gr0+tid],loc);
    out[(sb*T_+(T_-1))*NS_+ss]=pred;
  }
}

extern "C" void kernel_launch(void* const* d_in,const int* in_sizes,int n_in,
                              void* d_out,int out_size){
  (void)in_sizes;(void)n_in;(void)out_size;
  const float* dec_cont=(const float*)d_in[0];
  const float* one_off =(const float*)d_in[1];
  const float* ts      =(const float*)d_in[2];
  const float* emb0    =(const float*)d_in[3];
  const float* emb1    =(const float*)d_in[4];
  const float* Wih0    =(const float*)d_in[5];
  const float* Whh0    =(const float*)d_in[6];
  const float* bih0    =(const float*)d_in[7];
  const float* bhh0    =(const float*)d_in[8];
  const float* Wih1    =(const float*)d_in[9];
  const float* Whh1    =(const float*)d_in[10];
  const float* bih1    =(const float*)d_in[11];
  const float* bhh1    =(const float*)d_in[12];
  const float* Wproj   =(const float*)d_in[13];
  const float* bproj   =(const float*)d_in[14];
  const float* h0in    =(const float*)d_in[15];
  const float* c0in    =(const float*)d_in[16];
  const int*   dec_cat =(const int*)d_in[17];
  float* out=(float*)d_out;

  setup_kernel<<<4096+(T_*ROWS_TOTAL+255)/256,256>>>(dec_cont,emb0,emb1,Wih0,bih0,bhh0,dec_cat);

  cudaFuncSetAttribute(deepar_mma,cudaFuncAttributeMaxDynamicSharedMemorySize,SM_WORDS*4);
  deepar_mma<<<NCTA,TPB,SM_WORDS*4>>>(ts,one_off,Wih0,Whh0,Wih1,Whh1,
                                      bih1,bhh1,Wproj,bproj,h0in,c0in,out);
}